// round 9
// baseline (speedup 1.0000x reference)
#include <cuda_runtime.h>
#include <cuda_bf16.h>
#include <cstdint>
#include <cstddef>

// ---------------------------------------------------------------------------
// pre[b,o,d] = sum_{h,f} W[o, h*64+f] * x[b,h,d] * inp[b,f,d] + bias[o]
// x_next = relu(pre);  out[:, off+o] = sum_d relu(pre);  3 chained layers.
// B=512, F=64, D=32, O=128.
//
// GEMM per layer: D[o=128, n=(b*32+d)] = W[o,k] * Z[k,n], Z built in SMEM.
// mma.sync m16n8k16 bf16, 3-MMA split (Whi*Zhi + Whi*Zlo + Wlo*Zhi).
// Round-9: 3-STAGE pipeline (was 2). Producers run up to 2 tiles ahead so the
// producer latency chain (empty-wakeup + cp.async + Z-gen + full-wakeup) no
// longer sits on the consumer critical path every other tile.
// Warps 0-7 = MMA consumers (m32 x n64), warps 8-15 = producers.
// ---------------------------------------------------------------------------

#define SW128(o) ((o) ^ (((o) >> 3) & 0x70))

__device__ __align__(16) float g_x1[512 * 128 * 32];
__device__ __align__(16) float g_x2[512 * 128 * 32];
__device__ uint4 g_W0[128 * 4096 * 4 / 16];
__device__ uint4 g_W1[128 * 8192 * 4 / 16];
__device__ uint4 g_W2[128 * 8192 * 4 / 16];

__device__ __forceinline__ uint32_t smem_u32(const void* p) {
    uint32_t a;
    asm("{ .reg .u64 t; cvta.to.shared.u64 t, %1; cvt.u32.u64 %0, t; }"
        : "=r"(a) : "l"(p));
    return a;
}

__device__ __forceinline__ void split2(float z0, float z1,
                                       uint32_t& hi, uint32_t& lo) {
    __nv_bfloat162 h = __floats2bfloat162_rn(z0, z1);
    float2 hf = __bfloat1622float2(h);
    __nv_bfloat162 l = __floats2bfloat162_rn(z0 - hf.x, z1 - hf.y);
    hi = reinterpret_cast<uint32_t&>(h);
    lo = reinterpret_cast<uint32_t&>(l);
}

__device__ __forceinline__ void ldsm4(uint32_t r[4], uint32_t addr) {
    asm volatile("ldmatrix.sync.aligned.m8n8.x4.shared.b16 {%0,%1,%2,%3}, [%4];"
                 : "=r"(r[0]), "=r"(r[1]), "=r"(r[2]), "=r"(r[3]) : "r"(addr));
}

__device__ __forceinline__ void mma_bf16(float c[4], const uint32_t a[4],
                                         uint32_t b0, uint32_t b1) {
    asm volatile(
        "mma.sync.aligned.m16n8k16.row.col.f32.bf16.bf16.f32 "
        "{%0,%1,%2,%3}, {%4,%5,%6,%7}, {%8,%9}, {%0,%1,%2,%3};"
        : "+f"(c[0]), "+f"(c[1]), "+f"(c[2]), "+f"(c[3])
        : "r"(a[0]), "r"(a[1]), "r"(a[2]), "r"(a[3]), "r"(b0), "r"(b1));
}

// --------------------------- mbarrier helpers -------------------------------
#define MBAR_INIT(a, c) \
    asm volatile("mbarrier.init.shared.b64 [%0], %1;" :: "r"(a), "r"(c) : "memory")
#define MBAR_ARRIVE(a) \
    asm volatile("mbarrier.arrive.release.cta.shared::cta.b64 _, [%0];" :: "r"(a) : "memory")
#define MBAR_WAIT(a, p) do { uint32_t _m = (a); uint32_t _p = (p); uint32_t _d;      \
    asm volatile("{\n\t.reg .pred q;\n\t"                                            \
        "mbarrier.try_wait.parity.acquire.cta.shared::cta.b64 q, [%1], %2;\n\t"      \
        "selp.b32 %0,1,0,q;\n\t}" : "=r"(_d) : "r"(_m), "r"(_p) : "memory");         \
    if (!_d) {                                                                       \
        asm volatile("{\n\t.reg .pred q;\n\t"                                        \
            "WL%=:\n\t"                                                              \
            "mbarrier.try_wait.parity.acquire.cta.shared::cta.b64 q, [%0], %1, 0x989680;\n\t" \
            "@q bra.uni WD%=;\n\t"                                                   \
            "bra.uni WL%=;\n\t"                                                      \
            "WD%=:\n\t}" :: "r"(_m), "r"(_p) : "memory");                            \
    } } while (0)

// --------------------------- W prep: fp32 -> split bf16 tiles ---------------
__global__ __launch_bounds__(256)
void prep_w(const float* __restrict__ W, uint4* __restrict__ dst, int K) {
    int idx = blockIdx.x * 256 + threadIdx.x;
    int cpr = K >> 3;
    if (idx >= 128 * cpr) return;
    int o = idx / cpr;
    int k = (idx % cpr) * 8;
    const float4* src = (const float4*)(W + (size_t)o * K + k);
    float4 v0 = src[0], v1 = src[1];
    float zf[8] = {v0.x, v0.y, v0.z, v0.w, v1.x, v1.y, v1.z, v1.w};
    uint32_t hi[4], lo[4];
#pragma unroll
    for (int p = 0; p < 4; p++) split2(zf[2 * p], zf[2 * p + 1], hi[p], lo[p]);
    char* base = (char*)dst + (size_t)(k >> 6) * 32768;
    uint32_t off = SW128((uint32_t)(o * 128 + (k & 63) * 2));
    *(uint4*)(base + off)         = make_uint4(hi[0], hi[1], hi[2], hi[3]);
    *(uint4*)(base + 16384 + off) = make_uint4(lo[0], lo[1], lo[2], lo[3]);
}

// --------------------------- main layer kernel ------------------------------
// SMEM: [0,32768) inp_s; [32768 + s*65536), s=0..2: Whi Wlo Zhi Zlo (64K each)
//       [229376,229424): mbarriers full0..2, empty0..2
#define STAGE_OFF  32768
#define MB_OFF     229376
#define SMEM_TOTAL 229440

template <int H, bool WRITE_NEXT>
__global__ __launch_bounds__(512, 1)
void layer_mma(const float* __restrict__ x,
               const float* __restrict__ inp,
               const uint4* __restrict__ Wsp,
               const float* __restrict__ bias,
               float* __restrict__ x_next,
               float* __restrict__ out,
               int out_off)
{
    extern __shared__ char smem[];
    const uint32_t sb = smem_u32(smem);
    float* inp_s = (float*)smem;
    const int tid  = threadIdx.x;
    const int lane = tid & 31;
    const int w    = tid >> 5;
    const int b0   = blockIdx.x * 4;

    const uint32_t FULLB  = sb + MB_OFF;        // FULLB + 8*s
    const uint32_t EMPTYB = sb + MB_OFF + 24;   // EMPTYB + 8*s

    if (tid == 0) {
#pragma unroll
        for (int s = 0; s < 3; s++) {
            MBAR_INIT(FULLB + 8 * s, 8);
            MBAR_INIT(EMPTYB + 8 * s, 8);
        }
    }

    {   // stage inp (8192 floats, 512 threads -> 4 x float4 each)
        const float4* src = (const float4*)(inp + (size_t)b0 * 2048);
        float4* dst = (float4*)inp_s;
#pragma unroll
        for (int i = 0; i < 4; i++) dst[tid + i * 512] = src[tid + i * 512];
    }
    __syncthreads();   // inp_s + mbarriers ready

    if (w >= 8) {
        // ==================== PRODUCERS (warps 8-15) ====================
        const int ptid = tid - 256;                // 0..255
        const int n  = ptid & 127;
        const int bq = n >> 5;
        const int dd = n & 31;
        const int kh = (ptid >> 7) * 32;
        const float* xp = x + ((size_t)(b0 + bq) * H) * 32 + dd;
        const float* ip = inp_s + (size_t)bq * 2048 + kh * 32 + dd;
        const uint32_t zrow  = (uint32_t)n * 128;
        const uint32_t zmask = (uint32_t)((n & 7) << 4);
        const uint32_t zcol0 = (uint32_t)(kh * 2);
        const char* gW = (const char*)Wsp;

        for (int it = 0; it < H; ++it) {
            const int s = it % 3;
            const int u = it / 3;
            if (it >= 3) MBAR_WAIT(EMPTYB + 8 * s, (uint32_t)((u - 1) & 1));

            // W tile via cp.async (layout matches SMEM 1:1)
            {
                uint32_t dsb = sb + STAGE_OFF + s * 65536 + ptid * 16;
                const char* srcW = gW + (size_t)it * 32768 + ptid * 16;
#pragma unroll
                for (int i = 0; i < 8; i++)
                    asm volatile("cp.async.cg.shared.global [%0], [%1], 16;"
                                 :: "r"(dsb + i * 4096), "l"(srcW + i * 4096));
                asm volatile("cp.async.commit_group;");
            }
            // Z tile: z[n][k] = x[b,h,d] * inp[b, k, d], split hi/lo
            {
                char* zp = smem + STAGE_OFF + s * 65536 + 32768;
                const float xv = __ldg(xp + it * 32);
#pragma unroll
                for (int i = 0; i < 4; i++) {
                    float z[8];
#pragma unroll
                    for (int j = 0; j < 8; j++) z[j] = xv * ip[(i * 8 + j) * 32];
                    uint32_t hi[4], lo[4];
#pragma unroll
                    for (int p = 0; p < 4; p++)
                        split2(z[2 * p], z[2 * p + 1], hi[p], lo[p]);
                    uint32_t off = zrow + ((zcol0 + 16u * i) ^ zmask);
                    *(uint4*)(zp + off)         = make_uint4(hi[0], hi[1], hi[2], hi[3]);
                    *(uint4*)(zp + 16384 + off) = make_uint4(lo[0], lo[1], lo[2], lo[3]);
                }
            }
            asm volatile("cp.async.wait_group 0;");
            __syncwarp();
            if (lane == 0) MBAR_ARRIVE(FULLB + 8 * s);
        }
        return;   // producers exit
    }

    // ==================== CONSUMERS (warps 0-7) ====================
    const int wm = w & 3;     // m32 block
    const int wn = w >> 2;    // n64 block

    const int g = lane >> 3;
    const uint32_t maskL = (uint32_t)((lane & 7) << 4);
    uint32_t aRow[2], bRow[4], aCol[4], bCol[4];
#pragma unroll
    for (int mi = 0; mi < 2; mi++)
        aRow[mi] = (uint32_t)((32 * wm + 16 * mi + (lane & 7) + (g & 1) * 8) * 128);
#pragma unroll
    for (int p = 0; p < 4; p++)
        bRow[p] = (uint32_t)((64 * wn + 16 * p + 8 * ((g >> 1) & 1) + (lane & 7)) * 128);
#pragma unroll
    for (int kk = 0; kk < 4; kk++) {
        aCol[kk] = ((uint32_t)(((g >> 1) & 1) * 16 + 32 * kk)) ^ maskL;
        bCol[kk] = ((uint32_t)((g & 1) * 16 + 32 * kk)) ^ maskL;
    }

    float C[2][8][4];
#pragma unroll
    for (int i = 0; i < 2; i++)
#pragma unroll
        for (int j = 0; j < 8; j++)
#pragma unroll
            for (int q = 0; q < 4; q++) C[i][j][q] = 0.f;

    for (int it = 0; it < H; ++it) {
        const int s = it % 3;
        const int u = it / 3;
        MBAR_WAIT(FULLB + 8 * s, (uint32_t)(u & 1));

        const uint32_t st = sb + STAGE_OFF + s * 65536;
#pragma unroll
        for (int kk = 0; kk < 4; kk++) {
            uint32_t ah[2][4], al[2][4];
#pragma unroll
            for (int mi = 0; mi < 2; mi++) {
                ldsm4(ah[mi], st + aRow[mi] + aCol[kk]);
                ldsm4(al[mi], st + 16384 + aRow[mi] + aCol[kk]);
            }
#pragma unroll
            for (int p = 0; p < 4; p++) {
                uint32_t bh[4], bl[4];
                ldsm4(bh, st + 32768 + bRow[p] + bCol[kk]);
                ldsm4(bl, st + 49152 + bRow[p] + bCol[kk]);
#pragma unroll
                for (int mi = 0; mi < 2; mi++) {
#pragma unroll
                    for (int q = 0; q < 2; q++) {
                        float* c = C[mi][2 * p + q];
                        mma_bf16(c, ah[mi], bh[2 * q], bh[2 * q + 1]);
                        mma_bf16(c, ah[mi], bl[2 * q], bl[2 * q + 1]);
                        mma_bf16(c, al[mi], bh[2 * q], bh[2 * q + 1]);
                    }
                }
            }
        }
        __syncwarp();
        if (lane == 0) MBAR_ARRIVE(EMPTYB + 8 * s);
    }

    // Epilogue: bias + relu, write x_next, reduce over d -> out
    const int mrow = lane >> 2;
    const int qn   = lane & 3;
#pragma unroll
    for (int mi = 0; mi < 2; mi++) {
#pragma unroll
        for (int h2 = 0; h2 < 2; h2++) {
            const int o = 32 * wm + 16 * mi + 8 * h2 + mrow;
            const float bv = __ldg(bias + o);
#pragma unroll
            for (int bl2 = 0; bl2 < 2; bl2++) {
                const int b = b0 + 2 * wn + bl2;
                float sum = 0.f;
#pragma unroll
                for (int jj = 0; jj < 4; jj++) {
                    const int j = 4 * bl2 + jj;
                    float v0 = fmaxf(C[mi][j][2 * h2]     + bv, 0.f);
                    float v1 = fmaxf(C[mi][j][2 * h2 + 1] + bv, 0.f);
                    sum += v0 + v1;
                    if (WRITE_NEXT) {
                        const int d = 8 * jj + 2 * qn;
                        *(float2*)(x_next + ((size_t)b * 128 + o) * 32 + d) =
                            make_float2(v0, v1);
                    }
                }
                sum += __shfl_xor_sync(0xffffffffu, sum, 1);
                sum += __shfl_xor_sync(0xffffffffu, sum, 2);
                if (qn == 0) out[(size_t)b * 384 + out_off + o] = sum;
            }
        }
    }
}

// ---------------------------------------------------------------------------
extern "C" void kernel_launch(void* const* d_in, const int* in_sizes, int n_in,
                              void* d_out, int out_size)
{
    (void)in_sizes; (void)n_in; (void)out_size;
    const float* input = (const float*)d_in[0];
    const float* W0    = (const float*)d_in[1];
    const float* b0    = (const float*)d_in[2];
    const float* W1    = (const float*)d_in[3];
    const float* b1    = (const float*)d_in[4];
    const float* W2    = (const float*)d_in[5];
    const float* b2    = (const float*)d_in[6];
    float* out = (float*)d_out;

    float *x1, *x2; uint4 *w0p, *w1p, *w2p;
    cudaGetSymbolAddress((void**)&x1, g_x1);
    cudaGetSymbolAddress((void**)&x2, g_x2);
    cudaGetSymbolAddress((void**)&w0p, g_W0);
    cudaGetSymbolAddress((void**)&w1p, g_W1);
    cudaGetSymbolAddress((void**)&w2p, g_W2);

    cudaFuncSetAttribute(layer_mma<64,  true >, cudaFuncAttributeMaxDynamicSharedMemorySize, SMEM_TOTAL);
    cudaFuncSetAttribute(layer_mma<128, true >, cudaFuncAttributeMaxDynamicSharedMemorySize, SMEM_TOTAL);
    cudaFuncSetAttribute(layer_mma<128, false>, cudaFuncAttributeMaxDynamicSharedMemorySize, SMEM_TOTAL);

    prep_w<<<256, 256>>>(W0, w0p, 4096);
    prep_w<<<512, 256>>>(W1, w1p, 8192);
    prep_w<<<512, 256>>>(W2, w2p, 8192);

    dim3 grid(128), block(512);
    layer_mma<64,  true ><<<grid, block, SMEM_TOTAL>>>(input, input, w0p, b0, x1, out, 0);
    layer_mma<128, true ><<<grid, block, SMEM_TOTAL>>>(x1,    input, w1p, b1, x2, out, 128);
    layer_mma<128, false><<<grid, block, SMEM_TOTAL>>>(x2,    input, w2p, b2, nullptr, out, 256);
}

// round 10
// speedup vs baseline: 1.0346x; 1.0346x over previous
#include <cuda_runtime.h>
#include <cuda_bf16.h>
#include <cstdint>
#include <cstddef>

// ---------------------------------------------------------------------------
// pre[b,o,d] = sum_{h,f} W[o, h*64+f] * x[b,h,d] * inp[b,f,d] + bias[o]
// x_next = relu(pre);  out[:, off+o] = sum_d relu(pre);  3 chained layers.
// B=512, F=64, D=32, O=128.
//
// GEMM per layer: D[o=128, n=(b*32+d)] = W[o,k] * Z[k,n], Z built in SMEM.
// mma.sync m16n8k16 bf16, 3-MMA split (Whi*Zhi + Whi*Zlo + Wlo*Zhi).
// Round-10: 384 threads = 8 consumer warps + 4 producer warps. Fewer threads
// raises the per-thread register ceiling 128 -> 170 so the consumer can
// double-buffer B fragments (explicit LDSM pipelining) -- the 128-reg cap was
// forcing serialized LDSM->MMA per sub-step, draining the tensor pipe.
// ---------------------------------------------------------------------------

#define SW128(o) ((o) ^ (((o) >> 3) & 0x70))

__device__ __align__(16) float g_x1[512 * 128 * 32];
__device__ __align__(16) float g_x2[512 * 128 * 32];
__device__ uint4 g_W0[128 * 4096 * 4 / 16];
__device__ uint4 g_W1[128 * 8192 * 4 / 16];
__device__ uint4 g_W2[128 * 8192 * 4 / 16];

__device__ __forceinline__ uint32_t smem_u32(const void* p) {
    uint32_t a;
    asm("{ .reg .u64 t; cvta.to.shared.u64 t, %1; cvt.u32.u64 %0, t; }"
        : "=r"(a) : "l"(p));
    return a;
}

__device__ __forceinline__ void split2(float z0, float z1,
                                       uint32_t& hi, uint32_t& lo) {
    __nv_bfloat162 h = __floats2bfloat162_rn(z0, z1);
    float2 hf = __bfloat1622float2(h);
    __nv_bfloat162 l = __floats2bfloat162_rn(z0 - hf.x, z1 - hf.y);
    hi = reinterpret_cast<uint32_t&>(h);
    lo = reinterpret_cast<uint32_t&>(l);
}

__device__ __forceinline__ void ldsm4(uint32_t r[4], uint32_t addr) {
    asm volatile("ldmatrix.sync.aligned.m8n8.x4.shared.b16 {%0,%1,%2,%3}, [%4];"
                 : "=r"(r[0]), "=r"(r[1]), "=r"(r[2]), "=r"(r[3]) : "r"(addr));
}

__device__ __forceinline__ void mma_bf16(float c[4], const uint32_t a[4],
                                         uint32_t b0, uint32_t b1) {
    asm volatile(
        "mma.sync.aligned.m16n8k16.row.col.f32.bf16.bf16.f32 "
        "{%0,%1,%2,%3}, {%4,%5,%6,%7}, {%8,%9}, {%0,%1,%2,%3};"
        : "+f"(c[0]), "+f"(c[1]), "+f"(c[2]), "+f"(c[3])
        : "r"(a[0]), "r"(a[1]), "r"(a[2]), "r"(a[3]), "r"(b0), "r"(b1));
}

// --------------------------- mbarrier helpers -------------------------------
#define MBAR_INIT(a, c) \
    asm volatile("mbarrier.init.shared.b64 [%0], %1;" :: "r"(a), "r"(c) : "memory")
#define MBAR_ARRIVE(a) \
    asm volatile("mbarrier.arrive.release.cta.shared::cta.b64 _, [%0];" :: "r"(a) : "memory")
#define MBAR_WAIT(a, p) do { uint32_t _m = (a); uint32_t _p = (p); uint32_t _d;      \
    asm volatile("{\n\t.reg .pred q;\n\t"                                            \
        "mbarrier.try_wait.parity.acquire.cta.shared::cta.b64 q, [%1], %2;\n\t"      \
        "selp.b32 %0,1,0,q;\n\t}" : "=r"(_d) : "r"(_m), "r"(_p) : "memory");         \
    if (!_d) {                                                                       \
        asm volatile("{\n\t.reg .pred q;\n\t"                                        \
            "WL%=:\n\t"                                                              \
            "mbarrier.try_wait.parity.acquire.cta.shared::cta.b64 q, [%0], %1, 0x989680;\n\t" \
            "@q bra.uni WD%=;\n\t"                                                   \
            "bra.uni WL%=;\n\t"                                                      \
            "WD%=:\n\t}" :: "r"(_m), "r"(_p) : "memory");                            \
    } } while (0)

// --------------------------- W prep: fp32 -> split bf16 tiles ---------------
__global__ __launch_bounds__(256)
void prep_w(const float* __restrict__ W, uint4* __restrict__ dst, int K) {
    int idx = blockIdx.x * 256 + threadIdx.x;
    int cpr = K >> 3;
    if (idx >= 128 * cpr) return;
    int o = idx / cpr;
    int k = (idx % cpr) * 8;
    const float4* src = (const float4*)(W + (size_t)o * K + k);
    float4 v0 = src[0], v1 = src[1];
    float zf[8] = {v0.x, v0.y, v0.z, v0.w, v1.x, v1.y, v1.z, v1.w};
    uint32_t hi[4], lo[4];
#pragma unroll
    for (int p = 0; p < 4; p++) split2(zf[2 * p], zf[2 * p + 1], hi[p], lo[p]);
    char* base = (char*)dst + (size_t)(k >> 6) * 32768;
    uint32_t off = SW128((uint32_t)(o * 128 + (k & 63) * 2));
    *(uint4*)(base + off)         = make_uint4(hi[0], hi[1], hi[2], hi[3]);
    *(uint4*)(base + 16384 + off) = make_uint4(lo[0], lo[1], lo[2], lo[3]);
}

// --------------------------- main layer kernel ------------------------------
// SMEM: [0,32768) inp_s; [32768 + s*65536), s=0..2: Whi Wlo Zhi Zlo (64K each)
//       [229376,229424): mbarriers full0..2, empty0..2
#define STAGE_OFF  32768
#define MB_OFF     229376
#define SMEM_TOTAL 229440

template <int H, bool WRITE_NEXT>
__global__ __launch_bounds__(384, 1)
void layer_mma(const float* __restrict__ x,
               const float* __restrict__ inp,
               const uint4* __restrict__ Wsp,
               const float* __restrict__ bias,
               float* __restrict__ x_next,
               float* __restrict__ out,
               int out_off)
{
    extern __shared__ char smem[];
    const uint32_t sb = smem_u32(smem);
    float* inp_s = (float*)smem;
    const int tid  = threadIdx.x;
    const int lane = tid & 31;
    const int w    = tid >> 5;
    const int b0   = blockIdx.x * 4;

    const uint32_t FULLB  = sb + MB_OFF;        // FULLB + 8*s
    const uint32_t EMPTYB = sb + MB_OFF + 24;   // EMPTYB + 8*s

    if (tid == 0) {
#pragma unroll
        for (int s = 0; s < 3; s++) {
            MBAR_INIT(FULLB + 8 * s, 4);     // 4 producer warps
            MBAR_INIT(EMPTYB + 8 * s, 8);    // 8 consumer warps
        }
    }

    {   // stage inp (8192 floats = 2048 float4, 384 threads)
        const float4* src = (const float4*)(inp + (size_t)b0 * 2048);
        float4* dst = (float4*)inp_s;
        for (int i = tid; i < 2048; i += 384) dst[i] = src[i];
    }
    __syncthreads();   // inp_s + mbarriers ready

    if (w >= 8) {
        // ==================== PRODUCERS (warps 8-11) ====================
        const int n  = tid - 256;                  // 0..127 (full column)
        const int bq = n >> 5;
        const int dd = n & 31;
        const float* xp = x + ((size_t)(b0 + bq) * H) * 32 + dd;
        const float* ip = inp_s + (size_t)bq * 2048 + dd;
        const uint32_t zrow  = (uint32_t)n * 128;
        const uint32_t zmask = (uint32_t)((n & 7) << 4);
        const char* gW = (const char*)Wsp;

        for (int it = 0; it < H; ++it) {
            const int s = it % 3;
            const int u = it / 3;
            if (it >= 3) MBAR_WAIT(EMPTYB + 8 * s, (uint32_t)((u - 1) & 1));

            // W tile via cp.async (layout matches SMEM 1:1); 128 thr x 256 B
            {
                uint32_t dsb = sb + STAGE_OFF + s * 65536 + n * 16;
                const char* srcW = gW + (size_t)it * 32768 + n * 16;
#pragma unroll
                for (int i = 0; i < 16; i++)
                    asm volatile("cp.async.cg.shared.global [%0], [%1], 16;"
                                 :: "r"(dsb + i * 2048), "l"(srcW + i * 2048));
                asm volatile("cp.async.commit_group;");
            }
            // Z tile: whole 64-k column per thread, split hi/lo
            {
                char* zp = smem + STAGE_OFF + s * 65536 + 32768;
                const float xv = __ldg(xp + it * 32);
#pragma unroll
                for (int i = 0; i < 8; i++) {
                    float z[8];
#pragma unroll
                    for (int j = 0; j < 8; j++) z[j] = xv * ip[(i * 8 + j) * 32];
                    uint32_t hi[4], lo[4];
#pragma unroll
                    for (int p = 0; p < 4; p++)
                        split2(z[2 * p], z[2 * p + 1], hi[p], lo[p]);
                    uint32_t off = zrow + ((16u * i) ^ zmask);
                    *(uint4*)(zp + off)         = make_uint4(hi[0], hi[1], hi[2], hi[3]);
                    *(uint4*)(zp + 16384 + off) = make_uint4(lo[0], lo[1], lo[2], lo[3]);
                }
            }
            asm volatile("cp.async.wait_group 0;");
            __syncwarp();
            if (lane == 0) MBAR_ARRIVE(FULLB + 8 * s);
        }
        return;   // producers exit
    }

    // ==================== CONSUMERS (warps 0-7) ====================
    const int wm = w & 3;     // m32 block
    const int wn = w >> 2;    // n64 block

    const int g = lane >> 3;
    const uint32_t maskL = (uint32_t)((lane & 7) << 4);
    uint32_t aRow[2], bRow[4], aCol[4], bCol[4];
#pragma unroll
    for (int mi = 0; mi < 2; mi++)
        aRow[mi] = (uint32_t)((32 * wm + 16 * mi + (lane & 7) + (g & 1) * 8) * 128);
#pragma unroll
    for (int p = 0; p < 4; p++)
        bRow[p] = (uint32_t)((64 * wn + 16 * p + 8 * ((g >> 1) & 1) + (lane & 7)) * 128);
#pragma unroll
    for (int kk = 0; kk < 4; kk++) {
        aCol[kk] = ((uint32_t)(((g >> 1) & 1) * 16 + 32 * kk)) ^ maskL;
        bCol[kk] = ((uint32_t)((g & 1) * 16 + 32 * kk)) ^ maskL;
    }

    float C[2][8][4];
#pragma unroll
    for (int i = 0; i < 2; i++)
#pragma unroll
        for (int j = 0; j < 8; j++)
#pragma unroll
            for (int q = 0; q < 4; q++) C[i][j][q] = 0.f;

    for (int it = 0; it < H; ++it) {
        const int s = it % 3;
        const int u = it / 3;
        MBAR_WAIT(FULLB + 8 * s, (uint32_t)(u & 1));

        const uint32_t st = sb + STAGE_OFF + s * 65536;
#pragma unroll
        for (int kk = 0; kk < 4; kk++) {
            uint32_t ah[2][4], al[2][4];
#pragma unroll
            for (int mi = 0; mi < 2; mi++) {
                ldsm4(ah[mi], st + aRow[mi] + aCol[kk]);
                ldsm4(al[mi], st + 16384 + aRow[mi] + aCol[kk]);
            }
            // Double-buffered B fragments: load p+1 during p's MMAs.
            uint32_t bhA[4], blA[4], bhB[4], blB[4];
            ldsm4(bhA, st + 32768 + bRow[0] + bCol[kk]);
            ldsm4(blA, st + 49152 + bRow[0] + bCol[kk]);
#pragma unroll
            for (int p = 0; p < 4; p++) {
                uint32_t* bh = (p & 1) ? bhB : bhA;
                uint32_t* bl = (p & 1) ? blB : blA;
                uint32_t* bhn = (p & 1) ? bhA : bhB;
                uint32_t* bln = (p & 1) ? blA : blB;
                if (p < 3) {
                    ldsm4(bhn, st + 32768 + bRow[p + 1] + bCol[kk]);
                    ldsm4(bln, st + 49152 + bRow[p + 1] + bCol[kk]);
                }
#pragma unroll
                for (int mi = 0; mi < 2; mi++) {
#pragma unroll
                    for (int q = 0; q < 2; q++) {
                        float* c = C[mi][2 * p + q];
                        mma_bf16(c, ah[mi], bh[2 * q], bh[2 * q + 1]);
                        mma_bf16(c, ah[mi], bl[2 * q], bl[2 * q + 1]);
                        mma_bf16(c, al[mi], bh[2 * q], bh[2 * q + 1]);
                    }
                }
            }
        }
        __syncwarp();
        if (lane == 0) MBAR_ARRIVE(EMPTYB + 8 * s);
    }

    // Epilogue: bias + relu, write x_next, reduce over d -> out
    const int mrow = lane >> 2;
    const int qn   = lane & 3;
#pragma unroll
    for (int mi = 0; mi < 2; mi++) {
#pragma unroll
        for (int h2 = 0; h2 < 2; h2++) {
            const int o = 32 * wm + 16 * mi + 8 * h2 + mrow;
            const float bv = __ldg(bias + o);
#pragma unroll
            for (int bl2 = 0; bl2 < 2; bl2++) {
                const int b = b0 + 2 * wn + bl2;
                float sum = 0.f;
#pragma unroll
                for (int jj = 0; jj < 4; jj++) {
                    const int j = 4 * bl2 + jj;
                    float v0 = fmaxf(C[mi][j][2 * h2]     + bv, 0.f);
                    float v1 = fmaxf(C[mi][j][2 * h2 + 1] + bv, 0.f);
                    sum += v0 + v1;
                    if (WRITE_NEXT) {
                        const int d = 8 * jj + 2 * qn;
                        *(float2*)(x_next + ((size_t)b * 128 + o) * 32 + d) =
                            make_float2(v0, v1);
                    }
                }
                sum += __shfl_xor_sync(0xffffffffu, sum, 1);
                sum += __shfl_xor_sync(0xffffffffu, sum, 2);
                if (qn == 0) out[(size_t)b * 384 + out_off + o] = sum;
            }
        }
    }
}

// ---------------------------------------------------------------------------
extern "C" void kernel_launch(void* const* d_in, const int* in_sizes, int n_in,
                              void* d_out, int out_size)
{
    (void)in_sizes; (void)n_in; (void)out_size;
    const float* input = (const float*)d_in[0];
    const float* W0    = (const float*)d_in[1];
    const float* b0    = (const float*)d_in[2];
    const float* W1    = (const float*)d_in[3];
    const float* b1    = (const float*)d_in[4];
    const float* W2    = (const float*)d_in[5];
    const float* b2    = (const float*)d_in[6];
    float* out = (float*)d_out;

    float *x1, *x2; uint4 *w0p, *w1p, *w2p;
    cudaGetSymbolAddress((void**)&x1, g_x1);
    cudaGetSymbolAddress((void**)&x2, g_x2);
    cudaGetSymbolAddress((void**)&w0p, g_W0);
    cudaGetSymbolAddress((void**)&w1p, g_W1);
    cudaGetSymbolAddress((void**)&w2p, g_W2);

    cudaFuncSetAttribute(layer_mma<64,  true >, cudaFuncAttributeMaxDynamicSharedMemorySize, SMEM_TOTAL);
    cudaFuncSetAttribute(layer_mma<128, true >, cudaFuncAttributeMaxDynamicSharedMemorySize, SMEM_TOTAL);
    cudaFuncSetAttribute(layer_mma<128, false>, cudaFuncAttributeMaxDynamicSharedMemorySize, SMEM_TOTAL);

    prep_w<<<256, 256>>>(W0, w0p, 4096);
    prep_w<<<512, 256>>>(W1, w1p, 8192);
    prep_w<<<512, 256>>>(W2, w2p, 8192);

    dim3 grid(128), block(384);
    layer_mma<64,  true ><<<grid, block, SMEM_TOTAL>>>(input, input, w0p, b0, x1, out, 0);
    layer_mma<128, true ><<<grid, block, SMEM_TOTAL>>>(x1,    input, w1p, b1, x2, out, 128);
    layer_mma<128, false><<<grid, block, SMEM_TOTAL>>>(x2,    input, w2p, b2, nullptr, out, 256);
}

// round 11
// speedup vs baseline: 1.0346x; 1.0000x over previous
#include <cuda_runtime.h>
#include <cuda_bf16.h>
#include <cstdint>
#include <cstddef>

// ---------------------------------------------------------------------------
// pre[b,o,d] = sum_{h,f} W[o, h*64+f] * x[b,h,d] * inp[b,f,d] + bias[o]
// x_next = relu(pre);  out[:, off+o] = sum_d relu(pre);  3 chained layers.
// B=512, F=64, D=32, O=128.
//
// GEMM per layer: D[o=128, n=(b*32+d)] = W[o,k] * Z[k,n], Z built in SMEM.
// mma.sync m16n8k16 bf16, 3-MMA split (Whi*Zhi + Whi*Zlo + Wlo*Zhi).
// Round-11: TERM-MAJOR MMA ordering inside the warp-specialized consumer.
// Round-10's inner loop issued 3 consecutive MMAs on the same accumulator;
// with in-order issue + ~32cyc HMMA latency + only 2 consumer warps/SMSP,
// that RAW chain capped the tensor pipe at ~67%. Preload all fragments per
// k-step, then issue each split term across all 16 distinct accumulators
// (reuse distance 16). Per-accumulator add order unchanged -> bit-identical.
// ---------------------------------------------------------------------------

#define SW128(o) ((o) ^ (((o) >> 3) & 0x70))

__device__ __align__(16) float g_x1[512 * 128 * 32];
__device__ __align__(16) float g_x2[512 * 128 * 32];
__device__ uint4 g_W0[128 * 4096 * 4 / 16];
__device__ uint4 g_W1[128 * 8192 * 4 / 16];
__device__ uint4 g_W2[128 * 8192 * 4 / 16];

__device__ __forceinline__ uint32_t smem_u32(const void* p) {
    uint32_t a;
    asm("{ .reg .u64 t; cvta.to.shared.u64 t, %1; cvt.u32.u64 %0, t; }"
        : "=r"(a) : "l"(p));
    return a;
}

__device__ __forceinline__ void split2(float z0, float z1,
                                       uint32_t& hi, uint32_t& lo) {
    __nv_bfloat162 h = __floats2bfloat162_rn(z0, z1);
    float2 hf = __bfloat1622float2(h);
    __nv_bfloat162 l = __floats2bfloat162_rn(z0 - hf.x, z1 - hf.y);
    hi = reinterpret_cast<uint32_t&>(h);
    lo = reinterpret_cast<uint32_t&>(l);
}

__device__ __forceinline__ void ldsm4(uint32_t r[4], uint32_t addr) {
    asm volatile("ldmatrix.sync.aligned.m8n8.x4.shared.b16 {%0,%1,%2,%3}, [%4];"
                 : "=r"(r[0]), "=r"(r[1]), "=r"(r[2]), "=r"(r[3]) : "r"(addr));
}

__device__ __forceinline__ void mma_bf16(float c[4], const uint32_t a[4],
                                         uint32_t b0, uint32_t b1) {
    asm volatile(
        "mma.sync.aligned.m16n8k16.row.col.f32.bf16.bf16.f32 "
        "{%0,%1,%2,%3}, {%4,%5,%6,%7}, {%8,%9}, {%0,%1,%2,%3};"
        : "+f"(c[0]), "+f"(c[1]), "+f"(c[2]), "+f"(c[3])
        : "r"(a[0]), "r"(a[1]), "r"(a[2]), "r"(a[3]), "r"(b0), "r"(b1));
}

// --------------------------- mbarrier helpers -------------------------------
#define MBAR_INIT(a, c) \
    asm volatile("mbarrier.init.shared.b64 [%0], %1;" :: "r"(a), "r"(c) : "memory")
#define MBAR_ARRIVE(a) \
    asm volatile("mbarrier.arrive.release.cta.shared::cta.b64 _, [%0];" :: "r"(a) : "memory")
#define MBAR_WAIT(a, p) do { uint32_t _m = (a); uint32_t _p = (p); uint32_t _d;      \
    asm volatile("{\n\t.reg .pred q;\n\t"                                            \
        "mbarrier.try_wait.parity.acquire.cta.shared::cta.b64 q, [%1], %2;\n\t"      \
        "selp.b32 %0,1,0,q;\n\t}" : "=r"(_d) : "r"(_m), "r"(_p) : "memory");         \
    if (!_d) {                                                                       \
        asm volatile("{\n\t.reg .pred q;\n\t"                                        \
            "WL%=:\n\t"                                                              \
            "mbarrier.try_wait.parity.acquire.cta.shared::cta.b64 q, [%0], %1, 0x989680;\n\t" \
            "@q bra.uni WD%=;\n\t"                                                   \
            "bra.uni WL%=;\n\t"                                                      \
            "WD%=:\n\t}" :: "r"(_m), "r"(_p) : "memory");                            \
    } } while (0)

// --------------------------- W prep: fp32 -> split bf16 tiles ---------------
__global__ __launch_bounds__(256)
void prep_w(const float* __restrict__ W, uint4* __restrict__ dst, int K) {
    int idx = blockIdx.x * 256 + threadIdx.x;
    int cpr = K >> 3;
    if (idx >= 128 * cpr) return;
    int o = idx / cpr;
    int k = (idx % cpr) * 8;
    const float4* src = (const float4*)(W + (size_t)o * K + k);
    float4 v0 = src[0], v1 = src[1];
    float zf[8] = {v0.x, v0.y, v0.z, v0.w, v1.x, v1.y, v1.z, v1.w};
    uint32_t hi[4], lo[4];
#pragma unroll
    for (int p = 0; p < 4; p++) split2(zf[2 * p], zf[2 * p + 1], hi[p], lo[p]);
    char* base = (char*)dst + (size_t)(k >> 6) * 32768;
    uint32_t off = SW128((uint32_t)(o * 128 + (k & 63) * 2));
    *(uint4*)(base + off)         = make_uint4(hi[0], hi[1], hi[2], hi[3]);
    *(uint4*)(base + 16384 + off) = make_uint4(lo[0], lo[1], lo[2], lo[3]);
}

// --------------------------- main layer kernel ------------------------------
// SMEM: [0,32768) inp_s; [32768 + s*65536), s=0..2: Whi Wlo Zhi Zlo (64K each)
//       [229376,229424): mbarriers full0..2, empty0..2
#define STAGE_OFF  32768
#define MB_OFF     229376
#define SMEM_TOTAL 229440

template <int H, bool WRITE_NEXT>
__global__ __launch_bounds__(384, 1)
void layer_mma(const float* __restrict__ x,
               const float* __restrict__ inp,
               const uint4* __restrict__ Wsp,
               const float* __restrict__ bias,
               float* __restrict__ x_next,
               float* __restrict__ out,
               int out_off)
{
    extern __shared__ char smem[];
    const uint32_t sb = smem_u32(smem);
    float* inp_s = (float*)smem;
    const int tid  = threadIdx.x;
    const int lane = tid & 31;
    const int w    = tid >> 5;
    const int b0   = blockIdx.x * 4;

    const uint32_t FULLB  = sb + MB_OFF;        // FULLB + 8*s
    const uint32_t EMPTYB = sb + MB_OFF + 24;   // EMPTYB + 8*s

    if (tid == 0) {
#pragma unroll
        for (int s = 0; s < 3; s++) {
            MBAR_INIT(FULLB + 8 * s, 4);     // 4 producer warps
            MBAR_INIT(EMPTYB + 8 * s, 8);    // 8 consumer warps
        }
    }

    {   // stage inp (8192 floats = 2048 float4, 384 threads)
        const float4* src = (const float4*)(inp + (size_t)b0 * 2048);
        float4* dst = (float4*)inp_s;
        for (int i = tid; i < 2048; i += 384) dst[i] = src[i];
    }
    __syncthreads();   // inp_s + mbarriers ready

    if (w >= 8) {
        // ==================== PRODUCERS (warps 8-11) ====================
        const int n  = tid - 256;                  // 0..127 (full column)
        const int bq = n >> 5;
        const int dd = n & 31;
        const float* xp = x + ((size_t)(b0 + bq) * H) * 32 + dd;
        const float* ip = inp_s + (size_t)bq * 2048 + dd;
        const uint32_t zrow  = (uint32_t)n * 128;
        const uint32_t zmask = (uint32_t)((n & 7) << 4);
        const char* gW = (const char*)Wsp;

        for (int it = 0; it < H; ++it) {
            const int s = it % 3;
            const int u = it / 3;
            if (it >= 3) MBAR_WAIT(EMPTYB + 8 * s, (uint32_t)((u - 1) & 1));

            // W tile via cp.async (layout matches SMEM 1:1); 128 thr x 256 B
            {
                uint32_t dsb = sb + STAGE_OFF + s * 65536 + n * 16;
                const char* srcW = gW + (size_t)it * 32768 + n * 16;
#pragma unroll
                for (int i = 0; i < 16; i++)
                    asm volatile("cp.async.cg.shared.global [%0], [%1], 16;"
                                 :: "r"(dsb + i * 2048), "l"(srcW + i * 2048));
                asm volatile("cp.async.commit_group;");
            }
            // Z tile: whole 64-k column per thread, split hi/lo
            {
                char* zp = smem + STAGE_OFF + s * 65536 + 32768;
                const float xv = __ldg(xp + it * 32);
#pragma unroll
                for (int i = 0; i < 8; i++) {
                    float z[8];
#pragma unroll
                    for (int j = 0; j < 8; j++) z[j] = xv * ip[(i * 8 + j) * 32];
                    uint32_t hi[4], lo[4];
#pragma unroll
                    for (int p = 0; p < 4; p++)
                        split2(z[2 * p], z[2 * p + 1], hi[p], lo[p]);
                    uint32_t off = zrow + ((16u * i) ^ zmask);
                    *(uint4*)(zp + off)         = make_uint4(hi[0], hi[1], hi[2], hi[3]);
                    *(uint4*)(zp + 16384 + off) = make_uint4(lo[0], lo[1], lo[2], lo[3]);
                }
            }
            asm volatile("cp.async.wait_group 0;");
            __syncwarp();
            if (lane == 0) MBAR_ARRIVE(FULLB + 8 * s);
        }
        return;   // producers exit
    }

    // ==================== CONSUMERS (warps 0-7) ====================
    const int wm = w & 3;     // m32 block
    const int wn = w >> 2;    // n64 block

    const int g = lane >> 3;
    const uint32_t maskL = (uint32_t)((lane & 7) << 4);
    uint32_t aRow[2], bRow[4], aCol[4], bCol[4];
#pragma unroll
    for (int mi = 0; mi < 2; mi++)
        aRow[mi] = (uint32_t)((32 * wm + 16 * mi + (lane & 7) + (g & 1) * 8) * 128);
#pragma unroll
    for (int p = 0; p < 4; p++)
        bRow[p] = (uint32_t)((64 * wn + 16 * p + 8 * ((g >> 1) & 1) + (lane & 7)) * 128);
#pragma unroll
    for (int kk = 0; kk < 4; kk++) {
        aCol[kk] = ((uint32_t)(((g >> 1) & 1) * 16 + 32 * kk)) ^ maskL;
        bCol[kk] = ((uint32_t)((g & 1) * 16 + 32 * kk)) ^ maskL;
    }

    float C[2][8][4];
#pragma unroll
    for (int i = 0; i < 2; i++)
#pragma unroll
        for (int j = 0; j < 8; j++)
#pragma unroll
            for (int q = 0; q < 4; q++) C[i][j][q] = 0.f;

    for (int it = 0; it < H; ++it) {
        const int s = it % 3;
        const int u = it / 3;
        MBAR_WAIT(FULLB + 8 * s, (uint32_t)(u & 1));

        const uint32_t st = sb + STAGE_OFF + s * 65536;
#pragma unroll
        for (int kk = 0; kk < 4; kk++) {
            // Preload ALL fragments for this k-step
            uint32_t ah[2][4], al[2][4], bh[4][4], bl[4][4];
#pragma unroll
            for (int mi = 0; mi < 2; mi++) {
                ldsm4(ah[mi], st + aRow[mi] + aCol[kk]);
                ldsm4(al[mi], st + 16384 + aRow[mi] + aCol[kk]);
            }
#pragma unroll
            for (int p = 0; p < 4; p++) {
                ldsm4(bh[p], st + 32768 + bRow[p] + bCol[kk]);
                ldsm4(bl[p], st + 49152 + bRow[p] + bCol[kk]);
            }
            // term 1: Whi * Zhi  -- 16 distinct accumulators
#pragma unroll
            for (int p = 0; p < 4; p++)
#pragma unroll
                for (int mi = 0; mi < 2; mi++)
#pragma unroll
                    for (int q = 0; q < 2; q++)
                        mma_bf16(C[mi][2 * p + q], ah[mi],
                                 bh[p][2 * q], bh[p][2 * q + 1]);
            // term 2: Whi * Zlo
#pragma unroll
            for (int p = 0; p < 4; p++)
#pragma unroll
                for (int mi = 0; mi < 2; mi++)
#pragma unroll
                    for (int q = 0; q < 2; q++)
                        mma_bf16(C[mi][2 * p + q], ah[mi],
                                 bl[p][2 * q], bl[p][2 * q + 1]);
            // term 3: Wlo * Zhi
#pragma unroll
            for (int p = 0; p < 4; p++)
#pragma unroll
                for (int mi = 0; mi < 2; mi++)
#pragma unroll
                    for (int q = 0; q < 2; q++)
                        mma_bf16(C[mi][2 * p + q], al[mi],
                                 bh[p][2 * q], bh[p][2 * q + 1]);
        }
        __syncwarp();
        if (lane == 0) MBAR_ARRIVE(EMPTYB + 8 * s);
    }

    // Epilogue: bias + relu, write x_next, reduce over d -> out
    const int mrow = lane >> 2;
    const int qn   = lane & 3;
#pragma unroll
    for (int mi = 0; mi < 2; mi++) {
#pragma unroll
        for (int h2 = 0; h2 < 2; h2++) {
            const int o = 32 * wm + 16 * mi + 8 * h2 + mrow;
            const float bv = __ldg(bias + o);
#pragma unroll
            for (int bl2 = 0; bl2 < 2; bl2++) {
                const int b = b0 + 2 * wn + bl2;
                float sum = 0.f;
#pragma unroll
                for (int jj = 0; jj < 4; jj++) {
                    const int j = 4 * bl2 + jj;
                    float v0 = fmaxf(C[mi][j][2 * h2]     + bv, 0.f);
                    float v1 = fmaxf(C[mi][j][2 * h2 + 1] + bv, 0.f);
                    sum += v0 + v1;
                    if (WRITE_NEXT) {
                        const int d = 8 * jj + 2 * qn;
                        *(float2*)(x_next + ((size_t)b * 128 + o) * 32 + d) =
                            make_float2(v0, v1);
                    }
                }
                sum += __shfl_xor_sync(0xffffffffu, sum, 1);
                sum += __shfl_xor_sync(0xffffffffu, sum, 2);
                if (qn == 0) out[(size_t)b * 384 + out_off + o] = sum;
            }
        }
    }
}

// ---------------------------------------------------------------------------
extern "C" void kernel_launch(void* const* d_in, const int* in_sizes, int n_in,
                              void* d_out, int out_size)
{
    (void)in_sizes; (void)n_in; (void)out_size;
    const float* input = (const float*)d_in[0];
    const float* W0    = (const float*)d_in[1];
    const float* b0    = (const float*)d_in[2];
    const float* W1    = (const float*)d_in[3];
    const float* b1    = (const float*)d_in[4];
    const float* W2    = (const float*)d_in[5];
    const float* b2    = (const float*)d_in[6];
    float* out = (float*)d_out;

    float *x1, *x2; uint4 *w0p, *w1p, *w2p;
    cudaGetSymbolAddress((void**)&x1, g_x1);
    cudaGetSymbolAddress((void**)&x2, g_x2);
    cudaGetSymbolAddress((void**)&w0p, g_W0);
    cudaGetSymbolAddress((void**)&w1p, g_W1);
    cudaGetSymbolAddress((void**)&w2p, g_W2);

    cudaFuncSetAttribute(layer_mma<64,  true >, cudaFuncAttributeMaxDynamicSharedMemorySize, SMEM_TOTAL);
    cudaFuncSetAttribute(layer_mma<128, true >, cudaFuncAttributeMaxDynamicSharedMemorySize, SMEM_TOTAL);
    cudaFuncSetAttribute(layer_mma<128, false>, cudaFuncAttributeMaxDynamicSharedMemorySize, SMEM_TOTAL);

    prep_w<<<256, 256>>>(W0, w0p, 4096);
    prep_w<<<512, 256>>>(W1, w1p, 8192);
    prep_w<<<512, 256>>>(W2, w2p, 8192);

    dim3 grid(128), block(384);
    layer_mma<64,  true ><<<grid, block, SMEM_TOTAL>>>(input, input, w0p, b0, x1, out, 0);
    layer_mma<128, true ><<<grid, block, SMEM_TOTAL>>>(x1,    input, w1p, b1, x2, out, 128);
    layer_mma<128, false><<<grid, block, SMEM_TOTAL>>>(x2,    input, w2p, b2, nullptr, out, 256);
}

// round 12
// speedup vs baseline: 1.1117x; 1.0744x over previous
#include <cuda_runtime.h>
#include <cuda_bf16.h>
#include <cstdint>
#include <cstddef>

// ---------------------------------------------------------------------------
// pre[b,o,d] = sum_{h,f} W[o, h*64+f] * x[b,h,d] * inp[b,f,d] + bias[o]
// x_next = relu(pre);  out[:, off+o] = sum_d relu(pre);  3 chained layers.
// B=512, F=64, D=32, O=128.
//
// GEMM per layer: D[o=128, n=(b*32+d)] = W[o,k] * Z[k,n], Z built in SMEM.
// mma.sync m16n8k16 bf16, 3-MMA split (Whi*Zhi + Whi*Zlo + Wlo*Zhi).
// Round-12: LAYER-0 SYMMETRY FOLD. x==input in layer 0, so Z is symmetric in
// (h,f): fold W across the diagonal -> K 4096 -> 2112 (33 tiles), halving
// layer-0 tensor work. (All scheduling levers are exhausted: tensor ~67% is
// the sustained legacy-HMMA rate, schedule-invariant across 5 experiments.)
// ---------------------------------------------------------------------------

#define SW128(o) ((o) ^ (((o) >> 3) & 0x70))

#define K0SYM   2112          // padded folded K for layer 0 (33 tiles)
#define K0REAL  2080          // 64*65/2 real pairs

__device__ __align__(16) float g_x1[512 * 128 * 32];
__device__ __align__(16) float g_x2[512 * 128 * 32];
__device__ uint4 g_W0[33 * 32768 / 16];          // folded layer-0 tiles
__device__ uint4 g_W1[128 * 8192 * 4 / 16];
__device__ uint4 g_W2[128 * 8192 * 4 / 16];
__device__ unsigned short g_pair[K0SYM];         // k -> (i | j<<8)

__device__ __forceinline__ uint32_t smem_u32(const void* p) {
    uint32_t a;
    asm("{ .reg .u64 t; cvta.to.shared.u64 t, %1; cvt.u32.u64 %0, t; }"
        : "=r"(a) : "l"(p));
    return a;
}

__device__ __forceinline__ void split2(float z0, float z1,
                                       uint32_t& hi, uint32_t& lo) {
    __nv_bfloat162 h = __floats2bfloat162_rn(z0, z1);
    float2 hf = __bfloat1622float2(h);
    __nv_bfloat162 l = __floats2bfloat162_rn(z0 - hf.x, z1 - hf.y);
    hi = reinterpret_cast<uint32_t&>(h);
    lo = reinterpret_cast<uint32_t&>(l);
}

__device__ __forceinline__ void ldsm4(uint32_t r[4], uint32_t addr) {
    asm volatile("ldmatrix.sync.aligned.m8n8.x4.shared.b16 {%0,%1,%2,%3}, [%4];"
                 : "=r"(r[0]), "=r"(r[1]), "=r"(r[2]), "=r"(r[3]) : "r"(addr));
}

__device__ __forceinline__ void mma_bf16(float c[4], const uint32_t a[4],
                                         uint32_t b0, uint32_t b1) {
    asm volatile(
        "mma.sync.aligned.m16n8k16.row.col.f32.bf16.bf16.f32 "
        "{%0,%1,%2,%3}, {%4,%5,%6,%7}, {%8,%9}, {%0,%1,%2,%3};"
        : "+f"(c[0]), "+f"(c[1]), "+f"(c[2]), "+f"(c[3])
        : "r"(a[0]), "r"(a[1]), "r"(a[2]), "r"(a[3]), "r"(b0), "r"(b1));
}

// --------------------------- mbarrier helpers -------------------------------
#define MBAR_INIT(a, c) \
    asm volatile("mbarrier.init.shared.b64 [%0], %1;" :: "r"(a), "r"(c) : "memory")
#define MBAR_ARRIVE(a) \
    asm volatile("mbarrier.arrive.release.cta.shared::cta.b64 _, [%0];" :: "r"(a) : "memory")
#define MBAR_WAIT(a, p) do { uint32_t _m = (a); uint32_t _p = (p); uint32_t _d;      \
    asm volatile("{\n\t.reg .pred q;\n\t"                                            \
        "mbarrier.try_wait.parity.acquire.cta.shared::cta.b64 q, [%1], %2;\n\t"      \
        "selp.b32 %0,1,0,q;\n\t}" : "=r"(_d) : "r"(_m), "r"(_p) : "memory");         \
    if (!_d) {                                                                       \
        asm volatile("{\n\t.reg .pred q;\n\t"                                        \
            "WL%=:\n\t"                                                              \
            "mbarrier.try_wait.parity.acquire.cta.shared::cta.b64 q, [%0], %1, 0x989680;\n\t" \
            "@q bra.uni WD%=;\n\t"                                                   \
            "bra.uni WL%=;\n\t"                                                      \
            "WD%=:\n\t}" :: "r"(_m), "r"(_p) : "memory");                            \
    } } while (0)

// --------------------------- pair table (k -> (i,j), i<=j) ------------------
__global__ void init_pairs() {
    int k = blockIdx.x * 256 + threadIdx.x;
    if (k >= K0SYM) return;
    if (k < K0REAL) {
        int i = 0, base = 0;
        while (base + (64 - i) <= k) { base += 64 - i; i++; }
        int j = i + (k - base);
        g_pair[k] = (unsigned short)(i | (j << 8));
    } else {
        g_pair[k] = 0;
    }
}

// --------------------------- W prep: fp32 -> split bf16 tiles ---------------
__global__ __launch_bounds__(256)
void prep_w(const float* __restrict__ W, uint4* __restrict__ dst, int K) {
    int idx = blockIdx.x * 256 + threadIdx.x;
    int cpr = K >> 3;
    if (idx >= 128 * cpr) return;
    int o = idx / cpr;
    int k = (idx % cpr) * 8;
    const float4* src = (const float4*)(W + (size_t)o * K + k);
    float4 v0 = src[0], v1 = src[1];
    float zf[8] = {v0.x, v0.y, v0.z, v0.w, v1.x, v1.y, v1.z, v1.w};
    uint32_t hi[4], lo[4];
#pragma unroll
    for (int p = 0; p < 4; p++) split2(zf[2 * p], zf[2 * p + 1], hi[p], lo[p]);
    char* base = (char*)dst + (size_t)(k >> 6) * 32768;
    uint32_t off = SW128((uint32_t)(o * 128 + (k & 63) * 2));
    *(uint4*)(base + off)         = make_uint4(hi[0], hi[1], hi[2], hi[3]);
    *(uint4*)(base + 16384 + off) = make_uint4(lo[0], lo[1], lo[2], lo[3]);
}

// Folded layer-0 prep: c[k] = W[i*64+j] + W[j*64+i] (i<j), W[i*65] (i==j), 0 pad
__global__ __launch_bounds__(256)
void prep_w0_sym(const float* __restrict__ W, uint4* __restrict__ dst) {
    int idx = blockIdx.x * 256 + threadIdx.x;        // 128 o x 264 chunks
    if (idx >= 128 * (K0SYM / 8)) return;
    int o = idx / (K0SYM / 8);
    int k0 = (idx % (K0SYM / 8)) * 8;
    const float* Wo = W + (size_t)o * 4096;
    float zf[8];
#pragma unroll
    for (int t = 0; t < 8; t++) {
        int k = k0 + t;
        float c = 0.f;
        if (k < K0REAL) {
            int pr = g_pair[k];
            int i = pr & 255, j = pr >> 8;
            c = (i == j) ? Wo[i * 65] : (Wo[i * 64 + j] + Wo[j * 64 + i]);
        }
        zf[t] = c;
    }
    uint32_t hi[4], lo[4];
#pragma unroll
    for (int p = 0; p < 4; p++) split2(zf[2 * p], zf[2 * p + 1], hi[p], lo[p]);
    char* base = (char*)dst + (size_t)(k0 >> 6) * 32768;
    uint32_t off = SW128((uint32_t)(o * 128 + (k0 & 63) * 2));
    *(uint4*)(base + off)         = make_uint4(hi[0], hi[1], hi[2], hi[3]);
    *(uint4*)(base + 16384 + off) = make_uint4(lo[0], lo[1], lo[2], lo[3]);
}

// --------------------------- main layer kernel ------------------------------
// SMEM: [0,32768) inp_s; [32768 + s*65536), s=0..2: Whi Wlo Zhi Zlo (64K each)
//       [229376,229424): mbarriers full0..2, empty0..2
#define STAGE_OFF  32768
#define MB_OFF     229376
#define SMEM_TOTAL 229440

template <int NTILES, int H, bool SYM, bool WRITE_NEXT>
__global__ __launch_bounds__(384, 1)
void layer_mma(const float* __restrict__ x,
               const float* __restrict__ inp,
               const uint4* __restrict__ Wsp,
               const float* __restrict__ bias,
               float* __restrict__ x_next,
               float* __restrict__ out,
               int out_off)
{
    extern __shared__ char smem[];
    const uint32_t sb = smem_u32(smem);
    float* inp_s = (float*)smem;
    const int tid  = threadIdx.x;
    const int lane = tid & 31;
    const int w    = tid >> 5;
    const int b0   = blockIdx.x * 4;

    const uint32_t FULLB  = sb + MB_OFF;        // FULLB + 8*s
    const uint32_t EMPTYB = sb + MB_OFF + 24;   // EMPTYB + 8*s

    if (tid == 0) {
#pragma unroll
        for (int s = 0; s < 3; s++) {
            MBAR_INIT(FULLB + 8 * s, 4);     // 4 producer warps
            MBAR_INIT(EMPTYB + 8 * s, 8);    // 8 consumer warps
        }
    }

    {   // stage inp (8192 floats = 2048 float4, 384 threads)
        const float4* src = (const float4*)(inp + (size_t)b0 * 2048);
        float4* dst = (float4*)inp_s;
        for (int i = tid; i < 2048; i += 384) dst[i] = src[i];
    }
    __syncthreads();   // inp_s + mbarriers ready

    if (w >= 8) {
        // ==================== PRODUCERS (warps 8-11) ====================
        const int n  = tid - 256;                  // 0..127 (full column)
        const int bq = n >> 5;
        const int dd = n & 31;
        const float* xp = x + ((size_t)(b0 + bq) * H) * 32 + dd;
        const float* ip = inp_s + (size_t)bq * 2048 + dd;
        const uint32_t zrow  = (uint32_t)n * 128;
        const uint32_t zmask = (uint32_t)((n & 7) << 4);
        const char* gW = (const char*)Wsp;

        for (int it = 0; it < NTILES; ++it) {
            const int s = it % 3;
            const int u = it / 3;
            if (it >= 3) MBAR_WAIT(EMPTYB + 8 * s, (uint32_t)((u - 1) & 1));

            // W tile via cp.async (layout matches SMEM 1:1); 128 thr x 256 B
            {
                uint32_t dsb = sb + STAGE_OFF + s * 65536 + n * 16;
                const char* srcW = gW + (size_t)it * 32768 + n * 16;
#pragma unroll
                for (int i = 0; i < 16; i++)
                    asm volatile("cp.async.cg.shared.global [%0], [%1], 16;"
                                 :: "r"(dsb + i * 2048), "l"(srcW + i * 2048));
                asm volatile("cp.async.commit_group;");
            }
            // Z tile, split hi/lo
            {
                char* zp = smem + STAGE_OFF + s * 65536 + 32768;
                if (SYM) {
                    // layer 0: z[k] = inp_i * inp_j via pair table
#pragma unroll
                    for (int i = 0; i < 8; i++) {
                        float z[8];
#pragma unroll
                        for (int j = 0; j < 8; j++) {
                            int pr = __ldg(&g_pair[it * 64 + i * 8 + j]);
                            z[j] = ip[(pr & 255) * 32] * ip[(pr >> 8) * 32];
                        }
                        uint32_t hi[4], lo[4];
#pragma unroll
                        for (int p = 0; p < 4; p++)
                            split2(z[2 * p], z[2 * p + 1], hi[p], lo[p]);
                        uint32_t off = zrow + ((16u * i) ^ zmask);
                        *(uint4*)(zp + off)         = make_uint4(hi[0], hi[1], hi[2], hi[3]);
                        *(uint4*)(zp + 16384 + off) = make_uint4(lo[0], lo[1], lo[2], lo[3]);
                    }
                } else {
                    const float xv = __ldg(xp + it * 32);
#pragma unroll
                    for (int i = 0; i < 8; i++) {
                        float z[8];
#pragma unroll
                        for (int j = 0; j < 8; j++) z[j] = xv * ip[(i * 8 + j) * 32];
                        uint32_t hi[4], lo[4];
#pragma unroll
                        for (int p = 0; p < 4; p++)
                            split2(z[2 * p], z[2 * p + 1], hi[p], lo[p]);
                        uint32_t off = zrow + ((16u * i) ^ zmask);
                        *(uint4*)(zp + off)         = make_uint4(hi[0], hi[1], hi[2], hi[3]);
                        *(uint4*)(zp + 16384 + off) = make_uint4(lo[0], lo[1], lo[2], lo[3]);
                    }
                }
            }
            asm volatile("cp.async.wait_group 0;");
            __syncwarp();
            if (lane == 0) MBAR_ARRIVE(FULLB + 8 * s);
        }
        return;   // producers exit
    }

    // ==================== CONSUMERS (warps 0-7) ====================
    const int wm = w & 3;     // m32 block
    const int wn = w >> 2;    // n64 block

    const int g = lane >> 3;
    const uint32_t maskL = (uint32_t)((lane & 7) << 4);
    uint32_t aRow[2], bRow[4], aCol[4], bCol[4];
#pragma unroll
    for (int mi = 0; mi < 2; mi++)
        aRow[mi] = (uint32_t)((32 * wm + 16 * mi + (lane & 7) + (g & 1) * 8) * 128);
#pragma unroll
    for (int p = 0; p < 4; p++)
        bRow[p] = (uint32_t)((64 * wn + 16 * p + 8 * ((g >> 1) & 1) + (lane & 7)) * 128);
#pragma unroll
    for (int kk = 0; kk < 4; kk++) {
        aCol[kk] = ((uint32_t)(((g >> 1) & 1) * 16 + 32 * kk)) ^ maskL;
        bCol[kk] = ((uint32_t)((g & 1) * 16 + 32 * kk)) ^ maskL;
    }

    float C[2][8][4];
#pragma unroll
    for (int i = 0; i < 2; i++)
#pragma unroll
        for (int j = 0; j < 8; j++)
#pragma unroll
            for (int q = 0; q < 4; q++) C[i][j][q] = 0.f;

    for (int it = 0; it < NTILES; ++it) {
        const int s = it % 3;
        const int u = it / 3;
        MBAR_WAIT(FULLB + 8 * s, (uint32_t)(u & 1));

        const uint32_t st = sb + STAGE_OFF + s * 65536;
#pragma unroll
        for (int kk = 0; kk < 4; kk++) {
            uint32_t ah[2][4], al[2][4], bh[4][4], bl[4][4];
#pragma unroll
            for (int mi = 0; mi < 2; mi++) {
                ldsm4(ah[mi], st + aRow[mi] + aCol[kk]);
                ldsm4(al[mi], st + 16384 + aRow[mi] + aCol[kk]);
            }
#pragma unroll
            for (int p = 0; p < 4; p++) {
                ldsm4(bh[p], st + 32768 + bRow[p] + bCol[kk]);
                ldsm4(bl[p], st + 49152 + bRow[p] + bCol[kk]);
            }
#pragma unroll
            for (int p = 0; p < 4; p++)
#pragma unroll
                for (int mi = 0; mi < 2; mi++)
#pragma unroll
                    for (int q = 0; q < 2; q++)
                        mma_bf16(C[mi][2 * p + q], ah[mi],
                                 bh[p][2 * q], bh[p][2 * q + 1]);
#pragma unroll
            for (int p = 0; p < 4; p++)
#pragma unroll
                for (int mi = 0; mi < 2; mi++)
#pragma unroll
                    for (int q = 0; q < 2; q++)
                        mma_bf16(C[mi][2 * p + q], ah[mi],
                                 bl[p][2 * q], bl[p][2 * q + 1]);
#pragma unroll
            for (int p = 0; p < 4; p++)
#pragma unroll
                for (int mi = 0; mi < 2; mi++)
#pragma unroll
                    for (int q = 0; q < 2; q++)
                        mma_bf16(C[mi][2 * p + q], al[mi],
                                 bh[p][2 * q], bh[p][2 * q + 1]);
        }
        __syncwarp();
        if (lane == 0) MBAR_ARRIVE(EMPTYB + 8 * s);
    }

    // Epilogue: bias + relu, write x_next, reduce over d -> out
    const int mrow = lane >> 2;
    const int qn   = lane & 3;
#pragma unroll
    for (int mi = 0; mi < 2; mi++) {
#pragma unroll
        for (int h2 = 0; h2 < 2; h2++) {
            const int o = 32 * wm + 16 * mi + 8 * h2 + mrow;
            const float bv = __ldg(bias + o);
#pragma unroll
            for (int bl2 = 0; bl2 < 2; bl2++) {
                const int b = b0 + 2 * wn + bl2;
                float sum = 0.f;
#pragma unroll
                for (int jj = 0; jj < 4; jj++) {
                    const int j = 4 * bl2 + jj;
                    float v0 = fmaxf(C[mi][j][2 * h2]     + bv, 0.f);
                    float v1 = fmaxf(C[mi][j][2 * h2 + 1] + bv, 0.f);
                    sum += v0 + v1;
                    if (WRITE_NEXT) {
                        const int d = 8 * jj + 2 * qn;
                        *(float2*)(x_next + ((size_t)b * 128 + o) * 32 + d) =
                            make_float2(v0, v1);
                    }
                }
                sum += __shfl_xor_sync(0xffffffffu, sum, 1);
                sum += __shfl_xor_sync(0xffffffffu, sum, 2);
                if (qn == 0) out[(size_t)b * 384 + out_off + o] = sum;
            }
        }
    }
}

// ---------------------------------------------------------------------------
extern "C" void kernel_launch(void* const* d_in, const int* in_sizes, int n_in,
                              void* d_out, int out_size)
{
    (void)in_sizes; (void)n_in; (void)out_size;
    const float* input = (const float*)d_in[0];
    const float* W0    = (const float*)d_in[1];
    const float* b0    = (const float*)d_in[2];
    const float* W1    = (const float*)d_in[3];
    const float* b1    = (const float*)d_in[4];
    const float* W2    = (const float*)d_in[5];
    const float* b2    = (const float*)d_in[6];
    float* out = (float*)d_out;

    float *x1, *x2; uint4 *w0p, *w1p, *w2p;
    cudaGetSymbolAddress((void**)&x1, g_x1);
    cudaGetSymbolAddress((void**)&x2, g_x2);
    cudaGetSymbolAddress((void**)&w0p, g_W0);
    cudaGetSymbolAddress((void**)&w1p, g_W1);
    cudaGetSymbolAddress((void**)&w2p, g_W2);

    cudaFuncSetAttribute((const void*)layer_mma<33,  64,  true,  true >, cudaFuncAttributeMaxDynamicSharedMemorySize, SMEM_TOTAL);
    cudaFuncSetAttribute((const void*)layer_mma<128, 128, false, true >, cudaFuncAttributeMaxDynamicSharedMemorySize, SMEM_TOTAL);
    cudaFuncSetAttribute((const void*)layer_mma<128, 128, false, false>, cudaFuncAttributeMaxDynamicSharedMemorySize, SMEM_TOTAL);

    init_pairs<<<(K0SYM + 255) / 256, 256>>>();
    prep_w0_sym<<<(128 * (K0SYM / 8) + 255) / 256, 256>>>(W0, w0p);
    prep_w<<<512, 256>>>(W1, w1p, 8192);
    prep_w<<<512, 256>>>(W2, w2p, 8192);

    dim3 grid(128), block(384);
    layer_mma<33,  64,  true,  true ><<<grid, block, SMEM_TOTAL>>>(input, input, w0p, b0, x1, out, 0);
    layer_mma<128, 128, false, true ><<<grid, block, SMEM_TOTAL>>>(x1,    input, w1p, b1, x2, out, 128);
    layer_mma<128, 128, false, false><<<grid, block, SMEM_TOTAL>>>(x2,    input, w2p, b2, nullptr, out, 256);
}